// round 2
// baseline (speedup 1.0000x reference)
#include <cuda_runtime.h>
#include <cstdint>

#define B_DIM   8192
#define IN_DIM  2048
#define H_DIM   2048
#define K_TOTAL (IN_DIM + H_DIM)   // 4096
#define FOURH   (4 * H_DIM)        // 8192

#define BM 64
#define BN 64        // columns of H per CTA (x4 gates internally)
#define BK 16
#define ASTRIDE 20   // floats; 80B, 16B-aligned, conflict-free for A frags
#define BSTRIDE 72   // floats; 288B, 16B-aligned, conflict-free for B frags
#define NTHREADS 256
#define NT (K_TOTAL / BK)          // 256 k-iterations

__device__ __forceinline__ unsigned smem_u32(const void* p) {
    return (unsigned)__cvta_generic_to_shared(p);
}

__device__ __forceinline__ void cp_async16(unsigned dst, const void* src) {
    asm volatile("cp.async.cg.shared.global [%0], [%1], 16;\n" :: "r"(dst), "l"(src));
}

__device__ __forceinline__ unsigned f2tf32(float f) {
    unsigned r;
    asm("cvt.rna.tf32.f32 %0, %1;\n" : "=r"(r) : "f"(f));
    return r;
}

__device__ __forceinline__ void mma_m16n8k8_tf32(float c[4], const unsigned a[4],
                                                 unsigned b0, unsigned b1) {
    asm volatile(
        "mma.sync.aligned.m16n8k8.row.col.f32.tf32.tf32.f32 "
        "{%0,%1,%2,%3}, {%4,%5,%6,%7}, {%8,%9}, {%0,%1,%2,%3};\n"
        : "+f"(c[0]), "+f"(c[1]), "+f"(c[2]), "+f"(c[3])
        : "r"(a[0]), "r"(a[1]), "r"(a[2]), "r"(a[3]), "r"(b0), "r"(b1));
}

__device__ __forceinline__ float sigmoidf_(float x) {
    return 1.0f / (1.0f + expf(-x));
}

__global__ void __launch_bounds__(NTHREADS)
lstm_fused_kernel(const float* __restrict__ x,   // [B, IN]
                  const float* __restrict__ h1,  // [B, H]
                  const float* __restrict__ c1,  // [B, H]
                  const float* __restrict__ Wi,  // [IN, 4H]
                  const float* __restrict__ bi,  // [4H]
                  const float* __restrict__ Wh,  // [H, 4H]
                  const float* __restrict__ bh,  // [4H]
                  float* __restrict__ out)       // [3, B, H] = h, h, c
{
    __shared__ float As[2][BM * ASTRIDE];
    __shared__ float Bs[2][4 * BK * BSTRIDE];

    const int m0 = blockIdx.y * BM;   // batch-row tile
    const int n0 = blockIdx.x * BN;   // hidden-column tile
    const int tid  = threadIdx.x;
    const int warp = tid >> 5, lane = tid & 31;
    const int wm = warp >> 2, wn = warp & 3;     // 2 x 4 warp grid
    const int tg = lane >> 2, tig = lane & 3;

    // accumulators: [gate][mma_m][mma_n][4]
    float acc[4][2][2][4];
    #pragma unroll
    for (int g = 0; g < 4; g++)
        #pragma unroll
        for (int mm = 0; mm < 2; mm++)
            #pragma unroll
            for (int mn = 0; mn < 2; mn++)
                #pragma unroll
                for (int r = 0; r < 4; r++)
                    acc[g][mm][mn][r] = 0.0f;

    // loader thread mapping
    const int a_row = tid >> 2;            // 0..63
    const int a_kv  = (tid & 3) * 4;       // 0,4,8,12
    const int b_k   = tid >> 4;            // 0..15
    const int b_nv  = (tid & 15) * 4;      // 0..60

    auto load_stage = [&](int kt, int s) {
        const int k0 = kt * BK;
        // A = [x | h1], row-major
        const float* aptr;
        if (k0 < IN_DIM)
            aptr = x  + (size_t)(m0 + a_row) * IN_DIM + k0 + a_kv;
        else
            aptr = h1 + (size_t)(m0 + a_row) * H_DIM + (k0 - IN_DIM) + a_kv;
        cp_async16(smem_u32(&As[s][a_row * ASTRIDE + a_kv]), aptr);

        // W = [Wi ; Wh], row-major [K, 4H]; 4 gate sub-tiles
        const float* wrow = (k0 < IN_DIM)
            ? (Wi + (size_t)(k0 + b_k) * FOURH)
            : (Wh + (size_t)(k0 - IN_DIM + b_k) * FOURH);
        #pragma unroll
        for (int g = 0; g < 4; g++) {
            cp_async16(smem_u32(&Bs[s][g * BK * BSTRIDE + b_k * BSTRIDE + b_nv]),
                       wrow + g * H_DIM + n0 + b_nv);
        }
        asm volatile("cp.async.commit_group;\n");
    };

    load_stage(0, 0);

    for (int kt = 0; kt < NT; ++kt) {
        const int s = kt & 1;
        if (kt + 1 < NT) {
            load_stage(kt + 1, s ^ 1);
            asm volatile("cp.async.wait_group 1;\n");
        } else {
            asm volatile("cp.async.wait_group 0;\n");
        }
        __syncthreads();

        const float* Asm = As[s];
        const float* Bsm = Bs[s];

        #pragma unroll
        for (int ks = 0; ks < 2; ks++) {
            const int kk = ks * 8;
            // A fragments (shared across gates and mma_n)
            unsigned a[2][4];
            #pragma unroll
            for (int mm = 0; mm < 2; mm++) {
                const int rb = wm * 32 + mm * 16;
                a[mm][0] = f2tf32(Asm[(rb + tg    ) * ASTRIDE + kk + tig    ]);
                a[mm][1] = f2tf32(Asm[(rb + tg + 8) * ASTRIDE + kk + tig    ]);
                a[mm][2] = f2tf32(Asm[(rb + tg    ) * ASTRIDE + kk + tig + 4]);
                a[mm][3] = f2tf32(Asm[(rb + tg + 8) * ASTRIDE + kk + tig + 4]);
            }
            #pragma unroll
            for (int g = 0; g < 4; g++) {
                const float* Bg = Bsm + g * BK * BSTRIDE;
                #pragma unroll
                for (int mn = 0; mn < 2; mn++) {
                    const int cb = wn * 16 + mn * 8;
                    unsigned b0 = f2tf32(Bg[(kk + tig    ) * BSTRIDE + cb + tg]);
                    unsigned b1 = f2tf32(Bg[(kk + tig + 4) * BSTRIDE + cb + tg]);
                    #pragma unroll
                    for (int mm = 0; mm < 2; mm++)
                        mma_m16n8k8_tf32(acc[g][mm][mn], a[mm], b0, b1);
                }
            }
        }
        __syncthreads();
    }

    // ---- fused LSTM epilogue ----
    const size_t BH = (size_t)B_DIM * H_DIM;
    #pragma unroll
    for (int mn = 0; mn < 2; mn++) {
        const int col = n0 + wn * 16 + mn * 8 + tig * 2;  // even; col, col+1
        float bsum[4][2];
        #pragma unroll
        for (int g = 0; g < 4; g++) {
            bsum[g][0] = bi[g * H_DIM + col]     + bh[g * H_DIM + col];
            bsum[g][1] = bi[g * H_DIM + col + 1] + bh[g * H_DIM + col + 1];
        }
        #pragma unroll
        for (int mm = 0; mm < 2; mm++) {
            #pragma unroll
            for (int rr = 0; rr < 2; rr++) {
                const int row = m0 + wm * 32 + mm * 16 + tg + rr * 8;
                const size_t off = (size_t)row * H_DIM + col;
                const float2 cc1 = *(const float2*)(c1 + off);
                float hq[2], cq[2];
                #pragma unroll
                for (int q = 0; q < 2; q++) {
                    const int r = rr * 2 + q;
                    const float fpre = acc[0][mm][mn][r] + bsum[0][q];
                    const float ipre = acc[1][mm][mn][r] + bsum[1][q];
                    const float gpre = acc[2][mm][mn][r] + bsum[2][q];
                    const float opre = acc[3][mm][mn][r] + bsum[3][q];
                    const float ft = sigmoidf_(fpre);
                    const float it = sigmoidf_(ipre);
                    const float gt = tanhf(gpre);
                    const float ot = sigmoidf_(opre);
                    const float cprev = q ? cc1.y : cc1.x;
                    const float ct = ft * cprev + it * gt;
                    const float ht = ot * tanhf(ct);
                    hq[q] = ht; cq[q] = ct;
                }
                const float2 hv = make_float2(hq[0], hq[1]);
                const float2 cv = make_float2(cq[0], cq[1]);
                *(float2*)(out + off)            = hv;  // h_t (first copy)
                *(float2*)(out + BH + off)       = hv;  // h_t (second copy)
                *(float2*)(out + 2 * BH + off)   = cv;  // c_t
            }
        }
    }
}

extern "C" void kernel_launch(void* const* d_in, const int* in_sizes, int n_in,
                              void* d_out, int out_size) {
    const float* x  = (const float*)d_in[0];  // x_t  [B, IN]
    const float* h1 = (const float*)d_in[1];  // h_t1 [B, H]
    const float* c1 = (const float*)d_in[2];  // c_t1 [B, H]
    const float* Wi = (const float*)d_in[3];  // [IN, 4H]
    const float* bi = (const float*)d_in[4];  // [4H]
    const float* Wh = (const float*)d_in[5];  // [H, 4H]
    const float* bh = (const float*)d_in[6];  // [4H]
    float* out = (float*)d_out;               // [3, B, H]

    dim3 grid(H_DIM / BN, B_DIM / BM);  // (32, 128)
    lstm_fused_kernel<<<grid, NTHREADS>>>(x, h1, c1, Wi, bi, Wh, bh, out);
}

// round 5
// speedup vs baseline: 2.8481x; 2.8481x over previous
#include <cuda_runtime.h>
#include <cuda_fp16.h>
#include <cstdint>

#define B_DIM   8192
#define IN_DIM  2048
#define H_DIM   2048
#define K_TOTAL 4096
#define FOURH   8192

#define BM      128      // CTA rows
#define BNH     32       // CTA H-cols (x4 gates -> effN 128)
#define BK      64
#define NT      (K_TOTAL / BK)   // 64
#define NTHREADS 256

#define A_STAGE_BYTES 16384      // 128 x 64 halfs
#define B_STAGE_BYTES 16384      // 64 x 128 halfs
#define STAGE_BYTES   32768
#define NSTAGES 3
#define SMEM_TOTAL (NSTAGES * STAGE_BYTES)   // 98304

__device__ __half g_A[(size_t)B_DIM * K_TOTAL];   // [B, 4096] fp16
__device__ __half g_W[(size_t)K_TOTAL * FOURH];   // [4096, 8192] fp16 ([Wi;Wh])

__device__ __forceinline__ unsigned smem_u32(const void* p) {
    return (unsigned)__cvta_generic_to_shared(p);
}
__device__ __forceinline__ void cp_async16(unsigned dst, const void* src) {
    asm volatile("cp.async.cg.shared.global [%0], [%1], 16;\n" :: "r"(dst), "l"(src));
}
__device__ __forceinline__ void ldsm_x4(uint32_t r[4], uint32_t addr) {
    asm volatile("ldmatrix.sync.aligned.m8n8.x4.shared.b16 {%0,%1,%2,%3}, [%4];"
                 : "=r"(r[0]), "=r"(r[1]), "=r"(r[2]), "=r"(r[3]) : "r"(addr));
}
__device__ __forceinline__ void ldsm_x4_t(uint32_t r[4], uint32_t addr) {
    asm volatile("ldmatrix.sync.aligned.m8n8.x4.trans.shared.b16 {%0,%1,%2,%3}, [%4];"
                 : "=r"(r[0]), "=r"(r[1]), "=r"(r[2]), "=r"(r[3]) : "r"(addr));
}
__device__ __forceinline__ void mma_fp16(float c[4], const uint32_t a[4],
                                         uint32_t b0, uint32_t b1) {
    asm volatile(
        "mma.sync.aligned.m16n8k16.row.col.f32.f16.f16.f32 "
        "{%0,%1,%2,%3}, {%4,%5,%6,%7}, {%8,%9}, {%0,%1,%2,%3};\n"
        : "+f"(c[0]), "+f"(c[1]), "+f"(c[2]), "+f"(c[3])
        : "r"(a[0]), "r"(a[1]), "r"(a[2]), "r"(a[3]), "r"(b0), "r"(b1));
}
__device__ __forceinline__ float sigmoidf_(float x) { return 1.0f / (1.0f + expf(-x)); }

// ---- pre-pass 1: g_A = fp16([x | h1]), [B, 4096] ----
__global__ void __launch_bounds__(256) pack_A_kernel(const float* __restrict__ x,
                                                     const float* __restrict__ h1) {
    const int b = blockIdx.x;
    const float2* x2 = (const float2*)(x  + (size_t)b * IN_DIM);
    const float2* h2 = (const float2*)(h1 + (size_t)b * H_DIM);
    __half2* o2 = (__half2*)(g_A + (size_t)b * K_TOTAL);
    #pragma unroll
    for (int i = 0; i < 8; i++) {
        const int j = threadIdx.x + i * 256;          // 0..2047 half2 cols
        const float2 v = (j < 1024) ? x2[j] : h2[j - 1024];
        o2[j] = __floats2half2_rn(v.x, v.y);
    }
}

// ---- pre-pass 2: g_W[k][n] = fp16( k<2048 ? Wi[k][n] : Wh[k-2048][n] ) ----
__global__ void __launch_bounds__(256) pack_W_kernel(const float* __restrict__ Wi,
                                                     const float* __restrict__ Wh) {
    const int k = blockIdx.x;
    const float2* s2 = (const float2*)(((k < IN_DIM) ? Wi : (Wh - (size_t)IN_DIM * FOURH))
                                       + (size_t)k * FOURH);
    __half2* o2 = (__half2*)(g_W + (size_t)k * FOURH);
    #pragma unroll
    for (int i = 0; i < 16; i++) {
        const int j = threadIdx.x + i * 256;          // 0..4095 half2 cols
        const float2 v = s2[j];
        o2[j] = __floats2half2_rn(v.x, v.y);
    }
}

// ---- main: fp16 HMMA GEMM (ldmatrix + cp.async 3-stage) + LSTM epilogue ----
__global__ void __launch_bounds__(NTHREADS, 2)
lstm_main_kernel(const float* __restrict__ c1,
                 const float* __restrict__ bi,
                 const float* __restrict__ bh,
                 float* __restrict__ out) {
    extern __shared__ char smem[];
    const uint32_t sb = smem_u32(smem);
    const int tid = threadIdx.x;
    const int lane = tid & 31, wid = tid >> 5;
    const int wm = wid >> 1, wn = wid & 1;      // 4 x 2 warp grid
    const int m0 = blockIdx.y * BM;
    const int n0 = blockIdx.x * BNH;

    float acc[4][2][2][4];
    #pragma unroll
    for (int g = 0; g < 4; g++)
        #pragma unroll
        for (int mt = 0; mt < 2; mt++)
            #pragma unroll
            for (int nt = 0; nt < 2; nt++)
                #pragma unroll
                for (int r = 0; r < 4; r++)
                    acc[g][mt][nt][r] = 0.0f;

    auto load_stage = [&](int kt, int st) {
        const int k0 = kt * BK;
        const uint32_t ab = sb + st * STAGE_BYTES;
        const uint32_t bb = ab + A_STAGE_BYTES;
        #pragma unroll
        for (int i = 0; i < 4; i++) {
            // A chunk: 1024 x 16B; m = 0..127, c = 0..7 (8 halfs along k)
            const int ca = tid + i * NTHREADS;
            const int m = ca >> 3, c = ca & 7;
            cp_async16(ab + m * 128 + ((c ^ (m & 7)) << 4),
                       g_A + (size_t)(m0 + m) * K_TOTAL + k0 + c * 8);
            // B chunk: 1024 x 16B; k = 0..63, c2 = 0..15 (effN = g*32+nloc, g = c2>>2)
            const int k = ca >> 4, c2 = ca & 15;
            cp_async16(bb + k * 256 + ((c2 ^ (k & 7)) << 4),
                       g_W + (size_t)(k0 + k) * FOURH + (c2 >> 2) * H_DIM + n0 + (c2 & 3) * 8);
        }
        asm volatile("cp.async.commit_group;\n");
    };

    load_stage(0, 0);
    load_stage(1, 1);

    for (int kt = 0; kt < NT; ++kt) {
        if (kt + 1 < NT) asm volatile("cp.async.wait_group 1;\n");
        else             asm volatile("cp.async.wait_group 0;\n");
        __syncthreads();

        if (kt + 2 < NT) load_stage(kt + 2, (kt + 2) % NSTAGES);

        const uint32_t ab = sb + (kt % NSTAGES) * STAGE_BYTES;
        const uint32_t bb = ab + A_STAGE_BYTES;

        #pragma unroll
        for (int sub = 0; sub < 4; sub++) {
            const int kk = sub * 16;
            uint32_t a[2][4];
            #pragma unroll
            for (int mt = 0; mt < 2; mt++) {
                const int row = wm * 32 + mt * 16 + (lane & 15);
                const int ch  = (kk >> 3) + (lane >> 4);
                ldsm_x4(a[mt], ab + row * 128 + ((ch ^ (row & 7)) << 4));
            }
            #pragma unroll
            for (int g = 0; g < 4; g++) {
                uint32_t b[4];
                const int krow = kk + (lane & 15);
                const int ch   = g * 4 + wn * 2 + (lane >> 4);
                ldsm_x4_t(b, bb + krow * 256 + ((ch ^ (krow & 7)) << 4));
                #pragma unroll
                for (int mt = 0; mt < 2; mt++) {
                    mma_fp16(acc[g][mt][0], a[mt], b[0], b[1]);
                    mma_fp16(acc[g][mt][1], a[mt], b[2], b[3]);
                }
            }
        }
    }

    // ---- fused LSTM epilogue (pure register; thread owns all 4 gates) ----
    const size_t BH = (size_t)B_DIM * H_DIM;
    float bsum[4][2][2];   // [gate][nt][q]
    #pragma unroll
    for (int g = 0; g < 4; g++)
        #pragma unroll
        for (int nt = 0; nt < 2; nt++)
            #pragma unroll
            for (int q = 0; q < 2; q++) {
                const int col = g * H_DIM + n0 + wn * 16 + nt * 8 + (lane & 3) * 2 + q;
                bsum[g][nt][q] = bi[col] + bh[col];
            }

    #pragma unroll
    for (int mt = 0; mt < 2; mt++)
        #pragma unroll
        for (int nt = 0; nt < 2; nt++)
            #pragma unroll
            for (int rr = 0; rr < 2; rr++) {
                const int row = m0 + wm * 32 + mt * 16 + (lane >> 2) + rr * 8;
                const int col = n0 + wn * 16 + nt * 8 + (lane & 3) * 2;
                const size_t off = (size_t)row * H_DIM + col;
                const float2 cc = *(const float2*)(c1 + off);
                float hq[2], cq[2];
                #pragma unroll
                for (int q = 0; q < 2; q++) {
                    const int r = rr * 2 + q;
                    const float fpre = acc[0][mt][nt][r] + bsum[0][nt][q];
                    const float ipre = acc[1][mt][nt][r] + bsum[1][nt][q];
                    const float gpre = acc[2][mt][nt][r] + bsum[2][nt][q];
                    const float opre = acc[3][mt][nt][r] + bsum[3][nt][q];
                    const float ft = sigmoidf_(fpre);
                    const float it = sigmoidf_(ipre);
                    const float gt = tanhf(gpre);
                    const float ot = sigmoidf_(opre);
                    const float cprev = q ? cc.y : cc.x;
                    const float ct = ft * cprev + it * gt;
                    cq[q] = ct;
                    hq[q] = ot * tanhf(ct);
                }
                const float2 hv = make_float2(hq[0], hq[1]);
                const float2 cv = make_float2(cq[0], cq[1]);
                *(float2*)(out + off)          = hv;   // h_t
                *(float2*)(out + BH + off)     = hv;   // h_t copy
                *(float2*)(out + 2 * BH + off) = cv;   // c_t
            }
}

extern "C" void kernel_launch(void* const* d_in, const int* in_sizes, int n_in,
                              void* d_out, int out_size) {
    const float* x  = (const float*)d_in[0];
    const float* h1 = (const float*)d_in[1];
    const float* c1 = (const float*)d_in[2];
    const float* Wi = (const float*)d_in[3];
    const float* bi = (const float*)d_in[4];
    const float* Wh = (const float*)d_in[5];
    const float* bh = (const float*)d_in[6];
    float* out = (float*)d_out;

    cudaFuncSetAttribute(lstm_main_kernel,
                         cudaFuncAttributeMaxDynamicSharedMemorySize, SMEM_TOTAL);

    pack_A_kernel<<<B_DIM, 256>>>(x, h1);
    pack_W_kernel<<<K_TOTAL, 256>>>(Wi, Wh);

    dim3 grid(H_DIM / BNH, B_DIM / BM);   // (64, 64)
    lstm_main_kernel<<<grid, NTHREADS, SMEM_TOTAL>>>(c1, bi, bh, out);
}